// round 10
// baseline (speedup 1.0000x reference)
#include <cuda_runtime.h>
#include <math.h>

#define N_NODES  50000
#define N_EDGES  800000
#define N_GRAPHS 1000
#define F_INPUT  128
#define HID      64
#define OUT_F    16
#define BN_EPS   1e-5f
#define NBLK256  ((N_NODES + 255) / 256)   // 196

// ---------------- scratch (static device globals; no allocation) ------------
// NOTE: g_deg relies on static zero-init for the first call; fill_kernel
// re-zeroes it at the end of every call (same work every call, deterministic).
__device__ float g_B0[N_NODES * HID];      // v (post MLP, pre-BN)
__device__ float g_B1[N_NODES * HID];      // t (transformed features)
__device__ float g_stats[3 * 2 * HID];     // per-layer sum, sumsq
__device__ float g_pooled[N_GRAPHS * HID]; // segment max
// CSR scratch
__device__ int g_deg[N_NODES];
__device__ int g_off[N_NODES + 1];
__device__ int g_cur[N_NODES];
__device__ int g_csr[N_EDGES];
__device__ int g_bsum[NBLK256];

// ---------------- helpers ---------------------------------------------------
__device__ __forceinline__ void atomicMaxF(float* addr, float val) {
    if (val >= 0.f) atomicMax((int*)addr, __float_as_int(val));
    else            atomicMin((unsigned int*)addr, __float_as_uint(val));
}
__device__ __forceinline__ void add2(float2& a, const float2 b) {
    a.x += b.x; a.y += b.y;
}

// ---------------- CSR build -------------------------------------------------
__global__ void hist_kernel(const int* __restrict__ ei) {
    int e = blockIdx.x * blockDim.x + threadIdx.x;
    if (e < N_EDGES) atomicAdd(&g_deg[__ldg(&ei[N_EDGES + e])], 1);
}
// scanA: per-block degree sums (blocks < NBLK256) + init pooled/stats (all).
// grid = 250 blocks so 250*256 = 64000 covers g_pooled exactly.
__global__ void scanA_kernel() {
    __shared__ int sh[256];
    int tid = threadIdx.x;
    int gi = blockIdx.x * 256 + tid;
    if (gi < N_GRAPHS * HID) g_pooled[gi] = -INFINITY;
    if (gi < 3 * 2 * HID) g_stats[gi] = 0.f;
    if (blockIdx.x >= NBLK256) return;
    int n = blockIdx.x * 256 + tid;
    sh[tid] = (n < N_NODES) ? g_deg[n] : 0;
    __syncthreads();
    for (int s = 128; s > 0; s >>= 1) {
        if (tid < s) sh[tid] += sh[tid + s];
        __syncthreads();
    }
    if (tid == 0) g_bsum[blockIdx.x] = sh[0];
}
__global__ void scanC_kernel() {   // block offset + per-node offsets
    __shared__ int sh[256];
    __shared__ int boff_sh;
    int tid = threadIdx.x;
    int part = 0;
    for (int j = tid; j < blockIdx.x; j += 256) part += g_bsum[j];
    sh[tid] = part;
    __syncthreads();
    for (int s = 128; s > 0; s >>= 1) {
        if (tid < s) sh[tid] += sh[tid + s];
        __syncthreads();
    }
    if (tid == 0) boff_sh = sh[0];
    __syncthreads();
    int boff = boff_sh;
    int n = blockIdx.x * 256 + tid;
    int v = (n < N_NODES) ? g_deg[n] : 0;
    sh[tid] = v;
    __syncthreads();
    for (int d = 1; d < 256; d <<= 1) {
        int t = (tid >= d) ? sh[tid - d] : 0;
        __syncthreads();
        sh[tid] += t;
        __syncthreads();
    }
    if (n < N_NODES) {
        int off = boff + sh[tid] - v;
        g_off[n] = off;
        g_cur[n] = off;
    }
    if (blockIdx.x == NBLK256 - 1 && tid == 255)
        g_off[N_NODES] = boff + sh[255];
}
// fill: scatter src indices into CSR; also re-zero g_deg for the next call.
__global__ void fill_kernel(const int* __restrict__ ei) {
    int e = blockIdx.x * blockDim.x + threadIdx.x;
    if (e < N_NODES) g_deg[e] = 0;      // deg no longer needed this call
    if (e >= N_EDGES) return;
    int s = __ldg(&ei[e]);
    int d = __ldg(&ei[N_EDGES + e]);
    int pos = atomicAdd(&g_cur[d], 1);
    g_csr[pos] = s;
}

// ---------------- gemm1: t = (BN-affine(h)) @ W (+folded bias) -> B1 --------
// 128-row tile, 128 threads, 8x8 register blocking. (R6 config, unchanged.)
template <int IN_F, bool FOLDED>
__global__ void __launch_bounds__(128) gemm1_kernel(
    const float* __restrict__ h_in, const float* __restrict__ w,
    const float* __restrict__ gamma, const float* __restrict__ beta,
    int stats_layer)
{
    extern __shared__ float smem[];
    float* w_sh = smem;                 // [IN_F][HID]
    float* h_sh = smem + IN_F * HID;    // [128][IN_F]
    __shared__ float sc[HID], sf[HID], bias_sh[HID];
    int tid = threadIdx.x;

    if (FOLDED) {
        if (tid < HID) {
            const float* stats = g_stats + stats_layer * 2 * HID;
            float inv_n = 1.f / (float)N_NODES;
            float mu  = stats[tid] * inv_n;
            float var = stats[HID + tid] * inv_n - mu * mu;
            float s = gamma[tid] * rsqrtf(var + BN_EPS);
            sc[tid] = s;
            sf[tid] = beta[tid] - mu * s;
        }
        __syncthreads();
    }

    const float* h = FOLDED ? g_B0 : h_in;
    for (int i = tid; i < IN_F * HID / 4; i += 128) {
        float4 v = ((const float4*)w)[i];
        if (FOLDED) {
            float s = sc[(i * 4) >> 6];   // k index (row of W)
            v.x *= s; v.y *= s; v.z *= s; v.w *= s;
        }
        ((float4*)w_sh)[i] = v;
    }

    int rowbase = blockIdx.x * 128;
    int nrows = N_NODES - rowbase; if (nrows > 128) nrows = 128;
    const float4* hbase = (const float4*)(h + (long)rowbase * IN_F);
    for (int i = tid; i < 128 * IN_F / 4; i += 128) {
        int r = i / (IN_F / 4);
        ((float4*)h_sh)[i] = (r < nrows) ? hbase[i] : make_float4(0.f, 0.f, 0.f, 0.f);
    }

    if (FOLDED && tid < HID) {
        float b = 0.f;
#pragma unroll 8
        for (int k = 0; k < HID; k++)
            b += sf[k] * __ldg(&w[k * HID + tid]);
        bias_sh[tid] = b;
    }
    __syncthreads();

    int rg = tid >> 3, cg = tid & 7;
    int r0 = rg * 8, c0 = cg * 8;
    float acc[8][8];
#pragma unroll
    for (int r = 0; r < 8; r++)
#pragma unroll
        for (int j = 0; j < 8; j++) acc[r][j] = 0.f;

    for (int k = 0; k < IN_F; k += 4) {
        float4 av[8];
#pragma unroll
        for (int r = 0; r < 8; r++)
            av[r] = *(const float4*)&h_sh[(r0 + r) * IN_F + k];
#pragma unroll
        for (int kk = 0; kk < 4; kk++) {
            float4 w0 = *(const float4*)&w_sh[(k + kk) * HID + c0];
            float4 w1 = *(const float4*)&w_sh[(k + kk) * HID + c0 + 4];
#pragma unroll
            for (int r = 0; r < 8; r++) {
                float a = (kk == 0) ? av[r].x : (kk == 1) ? av[r].y
                         : (kk == 2) ? av[r].z : av[r].w;
                acc[r][0] += a * w0.x; acc[r][1] += a * w0.y;
                acc[r][2] += a * w0.z; acc[r][3] += a * w0.w;
                acc[r][4] += a * w1.x; acc[r][5] += a * w1.y;
                acc[r][6] += a * w1.z; acc[r][7] += a * w1.w;
            }
        }
    }

    float4 b0 = make_float4(0.f, 0.f, 0.f, 0.f), b1v = b0;
    if (FOLDED) {
        b0  = *(const float4*)&bias_sh[c0];
        b1v = *(const float4*)&bias_sh[c0 + 4];
    }
#pragma unroll
    for (int r = 0; r < 8; r++) {
        if (r0 + r < nrows) {
            long off = (long)(rowbase + r0 + r) * HID + c0;
            *(float4*)&g_B1[off] = make_float4(acc[r][0] + b0.x, acc[r][1] + b0.y,
                                               acc[r][2] + b0.z, acc[r][3] + b0.w);
            *(float4*)&g_B1[off + 4] = make_float4(acc[r][4] + b1v.x, acc[r][5] + b1v.y,
                                                   acc[r][6] + b1v.z, acc[r][7] + b1v.w);
        }
    }
}

// ---------------- fused agg + gemm2 (128-row tile, 128 threads) -------------
// Phase 1: warp-per-row gather (divergence-free: loop bound uniform per warp).
// Phase 2: v = relu(u @ w2 + b2) -> B0 (8x8 blocking); accumulate BN stats.
__global__ void __launch_bounds__(128) agg_gemm2_kernel(
    const float* __restrict__ b1, const float* __restrict__ w2,
    const float* __restrict__ b2, int layer)
{
    extern __shared__ float smem[];
    float* w_sh = smem;                 // [HID][HID]
    float* u_sh = smem + HID * HID;     // [128][HID]
    __shared__ float s_sum[HID];
    __shared__ float s_sq[HID];
    int tid = threadIdx.x;

    for (int i = tid; i < HID * HID / 4; i += 128)
        ((float4*)w_sh)[i] = ((const float4*)w2)[i];
    if (tid < HID) { s_sum[tid] = 0.f; s_sq[tid] = 0.f; }

    int rowbase = blockIdx.x * 128;
    int nrows = N_NODES - rowbase; if (nrows > 128) nrows = 128;

    // phase 1: warp-per-row gather. 4 warps; each warp owns rows warp, warp+4, ...
    {
        int warp = tid >> 5, lane = tid & 31;
        int c = lane * 2;                       // each lane: 2 consecutive floats
        float2 bb = *(const float2*)&b1[c];
        for (int row = warp; row < 128; row += 4) {
            float2 a = make_float2(0.f, 0.f);
            if (row < nrows) {
                int node = rowbase + row;
                a = __ldg((const float2*)&g_B1[(long)node * HID + c]);
                int p = g_off[node], end = g_off[node + 1];
                for (; p + 8 <= end; p += 8) {
                    int s0 = __ldg(&g_csr[p + 0]);
                    int s1 = __ldg(&g_csr[p + 1]);
                    int s2 = __ldg(&g_csr[p + 2]);
                    int s3 = __ldg(&g_csr[p + 3]);
                    int s4 = __ldg(&g_csr[p + 4]);
                    int s5 = __ldg(&g_csr[p + 5]);
                    int s6 = __ldg(&g_csr[p + 6]);
                    int s7 = __ldg(&g_csr[p + 7]);
                    float2 v0 = __ldg((const float2*)&g_B1[(long)s0 * HID + c]);
                    float2 v1 = __ldg((const float2*)&g_B1[(long)s1 * HID + c]);
                    float2 v2 = __ldg((const float2*)&g_B1[(long)s2 * HID + c]);
                    float2 v3 = __ldg((const float2*)&g_B1[(long)s3 * HID + c]);
                    float2 v4 = __ldg((const float2*)&g_B1[(long)s4 * HID + c]);
                    float2 v5 = __ldg((const float2*)&g_B1[(long)s5 * HID + c]);
                    float2 v6 = __ldg((const float2*)&g_B1[(long)s6 * HID + c]);
                    float2 v7 = __ldg((const float2*)&g_B1[(long)s7 * HID + c]);
                    add2(a, v0); add2(a, v1); add2(a, v2); add2(a, v3);
                    add2(a, v4); add2(a, v5); add2(a, v6); add2(a, v7);
                }
                for (; p + 2 <= end; p += 2) {
                    int s0 = __ldg(&g_csr[p + 0]);
                    int s1 = __ldg(&g_csr[p + 1]);
                    float2 v0 = __ldg((const float2*)&g_B1[(long)s0 * HID + c]);
                    float2 v1 = __ldg((const float2*)&g_B1[(long)s1 * HID + c]);
                    add2(a, v0); add2(a, v1);
                }
                if (p < end) {
                    int s0 = __ldg(&g_csr[p]);
                    add2(a, __ldg((const float2*)&g_B1[(long)s0 * HID + c]));
                }
                a.x = fmaxf(a.x + bb.x, 0.f);
                a.y = fmaxf(a.y + bb.y, 0.f);
            }
            *(float2*)&u_sh[row * HID + c] = a;
        }
    }
    __syncthreads();

    // phase 2: GEMM (8x8 per thread)
    int rg = tid >> 3, cg = tid & 7;
    int r0 = rg * 8, c0 = cg * 8;
    float acc[8][8];
#pragma unroll
    for (int r = 0; r < 8; r++)
#pragma unroll
        for (int j = 0; j < 8; j++) acc[r][j] = 0.f;

    for (int k = 0; k < HID; k += 4) {
        float4 av[8];
#pragma unroll
        for (int r = 0; r < 8; r++)
            av[r] = *(const float4*)&u_sh[(r0 + r) * HID + k];
#pragma unroll
        for (int kk = 0; kk < 4; kk++) {
            float4 w0 = *(const float4*)&w_sh[(k + kk) * HID + c0];
            float4 w1 = *(const float4*)&w_sh[(k + kk) * HID + c0 + 4];
#pragma unroll
            for (int r = 0; r < 8; r++) {
                float a = (kk == 0) ? av[r].x : (kk == 1) ? av[r].y
                         : (kk == 2) ? av[r].z : av[r].w;
                acc[r][0] += a * w0.x; acc[r][1] += a * w0.y;
                acc[r][2] += a * w0.z; acc[r][3] += a * w0.w;
                acc[r][4] += a * w1.x; acc[r][5] += a * w1.y;
                acc[r][6] += a * w1.z; acc[r][7] += a * w1.w;
            }
        }
    }

    float4 bb0 = *(const float4*)&b2[c0];
    float4 bb1 = *(const float4*)&b2[c0 + 4];
    float ls[8] = {0,0,0,0,0,0,0,0};
    float lq[8] = {0,0,0,0,0,0,0,0};
#pragma unroll
    for (int r = 0; r < 8; r++) {
        if (r0 + r < nrows) {
            float o[8];
            o[0] = fmaxf(acc[r][0] + bb0.x, 0.f); o[1] = fmaxf(acc[r][1] + bb0.y, 0.f);
            o[2] = fmaxf(acc[r][2] + bb0.z, 0.f); o[3] = fmaxf(acc[r][3] + bb0.w, 0.f);
            o[4] = fmaxf(acc[r][4] + bb1.x, 0.f); o[5] = fmaxf(acc[r][5] + bb1.y, 0.f);
            o[6] = fmaxf(acc[r][6] + bb1.z, 0.f); o[7] = fmaxf(acc[r][7] + bb1.w, 0.f);
            long off = (long)(rowbase + r0 + r) * HID + c0;
            *(float4*)&g_B0[off]     = make_float4(o[0], o[1], o[2], o[3]);
            *(float4*)&g_B0[off + 4] = make_float4(o[4], o[5], o[6], o[7]);
#pragma unroll
            for (int j = 0; j < 8; j++) { ls[j] += o[j]; lq[j] += o[j] * o[j]; }
        }
    }
#pragma unroll
    for (int j = 0; j < 8; j++) {
        atomicAdd(&s_sum[c0 + j], ls[j]);
        atomicAdd(&s_sq[c0 + j],  lq[j]);
    }
    __syncthreads();
    float* stats = g_stats + layer * 2 * HID;
    if (tid < HID) {
        atomicAdd(&stats[tid], s_sum[tid]);
        atomicAdd(&stats[HID + tid], s_sq[tid]);
    }
}

// ---------------- pool: run-length segment max (batch is sorted) ------------
__global__ void __launch_bounds__(256) pool_kernel(
    const int* __restrict__ batch,
    const float* __restrict__ gamma, const float* __restrict__ beta)
{
    __shared__ float sc[HID], sf[HID];
    int tid = threadIdx.x;
    if (tid < HID) {
        const float* stats = g_stats + 2 * 2 * HID;   // layer 2
        float inv_n = 1.f / (float)N_NODES;
        float mu  = stats[tid] * inv_n;
        float var = stats[HID + tid] * inv_n - mu * mu;
        float s = gamma[tid] * rsqrtf(var + BN_EPS);
        sc[tid] = s;
        sf[tid] = beta[tid] - mu * s;
    }
    __syncthreads();

    int base = blockIdx.x * 128;
    int r = tid >> 6;       // 0..3
    int c = tid & 63;
    float cur = -INFINITY;
    int curg = -1;
    int lim = base + 128; if (lim > N_NODES) lim = N_NODES;
    for (int n = base + r; n < lim; n += 4) {
        int g = __ldg(&batch[n]);
        float v = g_B0[(long)n * HID + c] * sc[c] + sf[c];
        if (g != curg) {
            if (curg >= 0) atomicMaxF(&g_pooled[curg * HID + c], cur);
            curg = g; cur = v;
        } else {
            cur = fmaxf(cur, v);
        }
    }
    if (curg >= 0) atomicMaxF(&g_pooled[curg * HID + c], cur);
}

// ---------------- head: relu(pooled@lin1+b1)@lin2+b2 ------------------------
__global__ void __launch_bounds__(128) head_kernel(
    const float* __restrict__ lin1_w, const float* __restrict__ lin1_b,
    const float* __restrict__ lin2_w, const float* __restrict__ lin2_b,
    float* __restrict__ out)
{
    __shared__ float w1_sh[HID * HID];
    __shared__ float w2_sh[HID * OUT_F];
    __shared__ float p_sh[4][HID];
    __shared__ float h_sh[4][HID];
    int tid = threadIdx.x, warp = tid >> 5, lane = tid & 31;

    for (int i = tid; i < HID * HID / 4; i += 128)
        ((float4*)w1_sh)[i] = ((const float4*)lin1_w)[i];
    for (int i = tid; i < HID * OUT_F / 4; i += 128)
        ((float4*)w2_sh)[i] = ((const float4*)lin2_w)[i];

    int g = blockIdx.x * 4 + warp;
    float p0 = g_pooled[g * HID + lane];
    float p1 = g_pooled[g * HID + lane + 32];
    if (!isfinite(p0)) p0 = 0.f;
    if (!isfinite(p1)) p1 = 0.f;
    p_sh[warp][lane] = p0;
    p_sh[warp][lane + 32] = p1;
    __syncthreads();

    float acc0 = lin1_b[lane], acc1 = lin1_b[lane + 32];
#pragma unroll 8
    for (int k = 0; k < HID; k++) {
        float pv = p_sh[warp][k];
        acc0 += pv * w1_sh[k * HID + lane];
        acc1 += pv * w1_sh[k * HID + lane + 32];
    }
    h_sh[warp][lane]      = fmaxf(acc0, 0.f);
    h_sh[warp][lane + 32] = fmaxf(acc1, 0.f);
    __syncwarp();

    if (lane < OUT_F) {
        float acc = lin2_b[lane];
#pragma unroll 8
        for (int k = 0; k < HID; k++)
            acc += h_sh[warp][k] * w2_sh[k * OUT_F + lane];
        out[g * OUT_F + lane] = acc;
    }
}

// ---------------- launch ----------------------------------------------------
extern "C" void kernel_launch(void* const* d_in, const int* in_sizes, int n_in,
                              void* d_out, int out_size)
{
    const float* x     = (const float*)d_in[0];
    const int*   ei    = (const int*)d_in[1];    // int32 (JAX x64 disabled)
    const int*   batch = (const int*)d_in[2];
    const float* l0_w1 = (const float*)d_in[3];
    const float* l0_b1 = (const float*)d_in[4];
    const float* l0_w2 = (const float*)d_in[5];
    const float* l0_b2 = (const float*)d_in[6];
    const float* l0_g  = (const float*)d_in[7];
    const float* l0_be = (const float*)d_in[8];
    const float* ws1   = (const float*)d_in[9];
    const float* bs1   = (const float*)d_in[10];
    const float* ws2   = (const float*)d_in[11];
    const float* bs2   = (const float*)d_in[12];
    const float* gms   = (const float*)d_in[13];
    const float* bts   = (const float*)d_in[14];
    const float* lin1w = (const float*)d_in[15];
    const float* lin1b = (const float*)d_in[16];
    const float* lin2w = (const float*)d_in[17];
    const float* lin2b = (const float*)d_in[18];
    float* out = (float*)d_out;

    const int TILE_BLOCKS = (N_NODES + 127) / 128;     // 391
    const int EDGE_BLOCKS = (N_EDGES + 255) / 256;     // 3125
    const int SCANA_BLOCKS = (N_GRAPHS * HID + 255) / 256;  // 250 (>= NBLK256)

    const int SMEM_G1_L0 = (F_INPUT * HID + 128 * F_INPUT) * 4;  // 96 KB
    const int SMEM_G1_LN = (HID * HID + 128 * HID) * 4;          // 48 KB
    const int SMEM_AG2   = (HID * HID + 128 * HID) * 4;          // 48 KB
    cudaFuncSetAttribute(gemm1_kernel<F_INPUT, false>,
                         cudaFuncAttributeMaxDynamicSharedMemorySize, SMEM_G1_L0);
    cudaFuncSetAttribute(gemm1_kernel<HID, true>,
                         cudaFuncAttributeMaxDynamicSharedMemorySize, SMEM_G1_LN);
    cudaFuncSetAttribute(agg_gemm2_kernel,
                         cudaFuncAttributeMaxDynamicSharedMemorySize, SMEM_AG2);

    // ---- CSR build (+ pooled/stats init riding on scanA; deg re-zeroed in fill)
    hist_kernel<<<EDGE_BLOCKS, 256>>>(ei);
    scanA_kernel<<<SCANA_BLOCKS, 256>>>();
    scanC_kernel<<<NBLK256, 256>>>();
    fill_kernel<<<EDGE_BLOCKS, 256>>>(ei);

    // ---- layer 0 (128 -> 64) ----
    gemm1_kernel<F_INPUT, false><<<TILE_BLOCKS, 128, SMEM_G1_L0>>>(
        x, l0_w1, nullptr, nullptr, 0);
    agg_gemm2_kernel<<<TILE_BLOCKS, 128, SMEM_AG2>>>(l0_b1, l0_w2, l0_b2, 0);

    // ---- layer 1 (64 -> 64), folds layer-0 BN into weights inline ----
    gemm1_kernel<HID, true><<<TILE_BLOCKS, 128, SMEM_G1_LN>>>(
        nullptr, ws1, l0_g, l0_be, 0);
    agg_gemm2_kernel<<<TILE_BLOCKS, 128, SMEM_AG2>>>(bs1, ws2, bs2, 1);

    // ---- layer 2 (64 -> 64), folds layer-1 BN inline ----
    gemm1_kernel<HID, true><<<TILE_BLOCKS, 128, SMEM_G1_LN>>>(
        nullptr, ws1 + HID * HID, gms, bts, 1);
    agg_gemm2_kernel<<<TILE_BLOCKS, 128, SMEM_AG2>>>(
        bs1 + HID, ws2 + HID * HID, bs2 + HID, 2);

    // ---- pool (computes layer-2 BN inline) + head ----
    pool_kernel<<<TILE_BLOCKS, 256>>>(batch, gms + HID, bts + HID);
    head_kernel<<<N_GRAPHS / 4, 128>>>(lin1w, lin1b, lin2w, lin2b, out);
}

// round 11
// speedup vs baseline: 1.3088x; 1.3088x over previous
#include <cuda_runtime.h>
#include <math.h>

#define N_NODES  50000
#define N_EDGES  800000
#define N_GRAPHS 1000
#define F_INPUT  128
#define HID      64
#define OUT_F    16
#define BN_EPS   1e-5f
#define NBLK256  ((N_NODES + 255) / 256)   // 196

// ---------------- scratch (static device globals; no allocation) ------------
// g_deg relies on static zero-init for the first call; fill_kernel re-zeroes
// it every call (same work every call, deterministic).
__device__ float g_BA[N_NODES * HID];      // ping buffer
__device__ float g_BB[N_NODES * HID];      // pong buffer
__device__ float g_stats[3 * 2 * HID];     // per-layer sum, sumsq
__device__ float g_pooled[N_GRAPHS * HID]; // segment max
// CSR scratch
__device__ int g_deg[N_NODES];
__device__ int g_off[N_NODES + 1];
__device__ int g_cur[N_NODES];
__device__ int g_csr[N_EDGES];
__device__ int g_bsum[NBLK256];

// ---------------- helpers ---------------------------------------------------
__device__ __forceinline__ void atomicMaxF(float* addr, float val) {
    if (val >= 0.f) atomicMax((int*)addr, __float_as_int(val));
    else            atomicMin((unsigned int*)addr, __float_as_uint(val));
}
__device__ __forceinline__ void add4(float4& a, const float4 b) {
    a.x += b.x; a.y += b.y; a.z += b.z; a.w += b.w;
}

// ---------------- CSR build -------------------------------------------------
__global__ void hist_kernel(const int* __restrict__ ei) {
    int e = blockIdx.x * blockDim.x + threadIdx.x;
    if (e < N_EDGES) atomicAdd(&g_deg[__ldg(&ei[N_EDGES + e])], 1);
}
// scanA: per-block degree sums (blocks < NBLK256) + init pooled/stats.
// grid = 250 blocks: 250*256 = 64000 covers g_pooled.
__global__ void scanA_kernel() {
    __shared__ int sh[256];
    int tid = threadIdx.x;
    int gi = blockIdx.x * 256 + tid;
    if (gi < N_GRAPHS * HID) g_pooled[gi] = -INFINITY;
    if (gi < 3 * 2 * HID) g_stats[gi] = 0.f;
    if (blockIdx.x >= NBLK256) return;
    int n = blockIdx.x * 256 + tid;
    sh[tid] = (n < N_NODES) ? g_deg[n] : 0;
    __syncthreads();
    for (int s = 128; s > 0; s >>= 1) {
        if (tid < s) sh[tid] += sh[tid + s];
        __syncthreads();
    }
    if (tid == 0) g_bsum[blockIdx.x] = sh[0];
}
__global__ void scanC_kernel() {
    __shared__ int sh[256];
    __shared__ int boff_sh;
    int tid = threadIdx.x;
    int part = 0;
    for (int j = tid; j < blockIdx.x; j += 256) part += g_bsum[j];
    sh[tid] = part;
    __syncthreads();
    for (int s = 128; s > 0; s >>= 1) {
        if (tid < s) sh[tid] += sh[tid + s];
        __syncthreads();
    }
    if (tid == 0) boff_sh = sh[0];
    __syncthreads();
    int boff = boff_sh;
    int n = blockIdx.x * 256 + tid;
    int v = (n < N_NODES) ? g_deg[n] : 0;
    sh[tid] = v;
    __syncthreads();
    for (int d = 1; d < 256; d <<= 1) {
        int t = (tid >= d) ? sh[tid - d] : 0;
        __syncthreads();
        sh[tid] += t;
        __syncthreads();
    }
    if (n < N_NODES) {
        int off = boff + sh[tid] - v;
        g_off[n] = off;
        g_cur[n] = off;
    }
    if (blockIdx.x == NBLK256 - 1 && tid == 255)
        g_off[N_NODES] = boff + sh[255];
}
__global__ void fill_kernel(const int* __restrict__ ei) {
    int e = blockIdx.x * blockDim.x + threadIdx.x;
    if (e < N_NODES) g_deg[e] = 0;      // reset for next call
    if (e >= N_EDGES) return;
    int s = __ldg(&ei[e]);
    int d = __ldg(&ei[N_EDGES + e]);
    int pos = atomicAdd(&g_cur[d], 1);
    g_csr[pos] = s;
}

// ---------------- gemm1_L0: B1 = x @ l0_w1 (128->64) ------------------------
// 128-row tile, 128 threads, 8x8 register blocking (R6-proven config).
__global__ void __launch_bounds__(128) gemm1_l0_kernel(
    const float* __restrict__ h, const float* __restrict__ w)
{
    extern __shared__ float smem[];
    float* w_sh = smem;                     // [128][64]
    float* h_sh = smem + F_INPUT * HID;     // [128][128]
    int tid = threadIdx.x;

    for (int i = tid; i < F_INPUT * HID / 4; i += 128)
        ((float4*)w_sh)[i] = ((const float4*)w)[i];

    int rowbase = blockIdx.x * 128;
    int nrows = N_NODES - rowbase; if (nrows > 128) nrows = 128;
    const float4* hbase = (const float4*)(h + (long)rowbase * F_INPUT);
    for (int i = tid; i < 128 * F_INPUT / 4; i += 128) {
        int r = i / (F_INPUT / 4);
        ((float4*)h_sh)[i] = (r < nrows) ? hbase[i] : make_float4(0.f, 0.f, 0.f, 0.f);
    }
    __syncthreads();

    int rg = tid >> 3, cg = tid & 7;
    int r0 = rg * 8, c0 = cg * 8;
    float acc[8][8];
#pragma unroll
    for (int r = 0; r < 8; r++)
#pragma unroll
        for (int j = 0; j < 8; j++) acc[r][j] = 0.f;

    for (int k = 0; k < F_INPUT; k += 4) {
        float4 av[8];
#pragma unroll
        for (int r = 0; r < 8; r++)
            av[r] = *(const float4*)&h_sh[(r0 + r) * F_INPUT + k];
#pragma unroll
        for (int kk = 0; kk < 4; kk++) {
            float4 w0 = *(const float4*)&w_sh[(k + kk) * HID + c0];
            float4 w1 = *(const float4*)&w_sh[(k + kk) * HID + c0 + 4];
#pragma unroll
            for (int r = 0; r < 8; r++) {
                float a = (kk == 0) ? av[r].x : (kk == 1) ? av[r].y
                         : (kk == 2) ? av[r].z : av[r].w;
                acc[r][0] += a * w0.x; acc[r][1] += a * w0.y;
                acc[r][2] += a * w0.z; acc[r][3] += a * w0.w;
                acc[r][4] += a * w1.x; acc[r][5] += a * w1.y;
                acc[r][6] += a * w1.z; acc[r][7] += a * w1.w;
            }
        }
    }
#pragma unroll
    for (int r = 0; r < 8; r++) {
        if (r0 + r < nrows) {
            long off = (long)(rowbase + r0 + r) * HID + c0;
            *(float4*)&g_BB[off]     = make_float4(acc[r][0], acc[r][1], acc[r][2], acc[r][3]);
            *(float4*)&g_BB[off + 4] = make_float4(acc[r][4], acc[r][5], acc[r][6], acc[r][7]);
        }
    }
}

// ---------------- layer-0 fused agg + gemm2 (R6-exact gather) ---------------
// reads g_BB (t0), writes g_BA (v0), stats layer 0.
__global__ void __launch_bounds__(128) agg_gemm2_l0_kernel(
    const float* __restrict__ b1, const float* __restrict__ w2,
    const float* __restrict__ b2)
{
    extern __shared__ float smem[];
    float* w_sh = smem;                 // [64][64]
    float* u_sh = smem + HID * HID;     // [128][64]
    __shared__ float s_sum[HID];
    __shared__ float s_sq[HID];
    int tid = threadIdx.x;

    for (int i = tid; i < HID * HID / 4; i += 128)
        ((float4*)w_sh)[i] = ((const float4*)w2)[i];
    if (tid < HID) { s_sum[tid] = 0.f; s_sq[tid] = 0.f; }

    int rowbase = blockIdx.x * 128;
    int nrows = N_NODES - rowbase; if (nrows > 128) nrows = 128;

    // gather: 1024 tasks (128 rows x 8 slices), 8 per thread
    for (int it = 0; it < 8; it++) {
        int task = it * 128 + tid;
        int row = task >> 3;
        int c = (task & 7) * 8;
        float4 a0 = make_float4(0.f, 0.f, 0.f, 0.f), a1 = a0;
        if (row < nrows) {
            int node = rowbase + row;
            long base = (long)node * HID + c;
            a0 = *(const float4*)&g_BB[base];
            a1 = *(const float4*)&g_BB[base + 4];
            int p = g_off[node], end = g_off[node + 1];
            for (; p + 2 <= end; p += 2) {
                int s0 = __ldg(&g_csr[p]);
                int s1 = __ldg(&g_csr[p + 1]);
                const float4* t0 = (const float4*)(g_BB + (long)s0 * HID + c);
                const float4* t1 = (const float4*)(g_BB + (long)s1 * HID + c);
                float4 v00 = __ldg(t0), v01 = __ldg(t0 + 1);
                float4 v10 = __ldg(t1), v11 = __ldg(t1 + 1);
                add4(a0, v00); add4(a1, v01);
                add4(a0, v10); add4(a1, v11);
            }
            if (p < end) {
                int s0 = __ldg(&g_csr[p]);
                const float4* t0 = (const float4*)(g_BB + (long)s0 * HID + c);
                add4(a0, __ldg(t0)); add4(a1, __ldg(t0 + 1));
            }
            float4 bb0 = *(const float4*)&b1[c];
            float4 bb1 = *(const float4*)&b1[c + 4];
            a0.x = fmaxf(a0.x + bb0.x, 0.f); a0.y = fmaxf(a0.y + bb0.y, 0.f);
            a0.z = fmaxf(a0.z + bb0.z, 0.f); a0.w = fmaxf(a0.w + bb0.w, 0.f);
            a1.x = fmaxf(a1.x + bb1.x, 0.f); a1.y = fmaxf(a1.y + bb1.y, 0.f);
            a1.z = fmaxf(a1.z + bb1.z, 0.f); a1.w = fmaxf(a1.w + bb1.w, 0.f);
        }
        *(float4*)&u_sh[row * HID + c]     = a0;
        *(float4*)&u_sh[row * HID + c + 4] = a1;
    }
    __syncthreads();

    // GEMM2 (8x8 per thread)
    int rg = tid >> 3, cg = tid & 7;
    int r0 = rg * 8, c0 = cg * 8;
    float acc[8][8];
#pragma unroll
    for (int r = 0; r < 8; r++)
#pragma unroll
        for (int j = 0; j < 8; j++) acc[r][j] = 0.f;

    for (int k = 0; k < HID; k += 4) {
        float4 av[8];
#pragma unroll
        for (int r = 0; r < 8; r++)
            av[r] = *(const float4*)&u_sh[(r0 + r) * HID + k];
#pragma unroll
        for (int kk = 0; kk < 4; kk++) {
            float4 w0 = *(const float4*)&w_sh[(k + kk) * HID + c0];
            float4 w1 = *(const float4*)&w_sh[(k + kk) * HID + c0 + 4];
#pragma unroll
            for (int r = 0; r < 8; r++) {
                float a = (kk == 0) ? av[r].x : (kk == 1) ? av[r].y
                         : (kk == 2) ? av[r].z : av[r].w;
                acc[r][0] += a * w0.x; acc[r][1] += a * w0.y;
                acc[r][2] += a * w0.z; acc[r][3] += a * w0.w;
                acc[r][4] += a * w1.x; acc[r][5] += a * w1.y;
                acc[r][6] += a * w1.z; acc[r][7] += a * w1.w;
            }
        }
    }

    float4 bb0 = *(const float4*)&b2[c0];
    float4 bb1 = *(const float4*)&b2[c0 + 4];
    float ls[8] = {0,0,0,0,0,0,0,0};
    float lq[8] = {0,0,0,0,0,0,0,0};
#pragma unroll
    for (int r = 0; r < 8; r++) {
        if (r0 + r < nrows) {
            float o[8];
            o[0] = fmaxf(acc[r][0] + bb0.x, 0.f); o[1] = fmaxf(acc[r][1] + bb0.y, 0.f);
            o[2] = fmaxf(acc[r][2] + bb0.z, 0.f); o[3] = fmaxf(acc[r][3] + bb0.w, 0.f);
            o[4] = fmaxf(acc[r][4] + bb1.x, 0.f); o[5] = fmaxf(acc[r][5] + bb1.y, 0.f);
            o[6] = fmaxf(acc[r][6] + bb1.z, 0.f); o[7] = fmaxf(acc[r][7] + bb1.w, 0.f);
            long off = (long)(rowbase + r0 + r) * HID + c0;
            *(float4*)&g_BA[off]     = make_float4(o[0], o[1], o[2], o[3]);
            *(float4*)&g_BA[off + 4] = make_float4(o[4], o[5], o[6], o[7]);
#pragma unroll
            for (int j = 0; j < 8; j++) { ls[j] += o[j]; lq[j] += o[j] * o[j]; }
        }
    }
#pragma unroll
    for (int j = 0; j < 8; j++) {
        atomicAdd(&s_sum[c0 + j], ls[j]);
        atomicAdd(&s_sq[c0 + j],  lq[j]);
    }
    __syncthreads();
    if (tid < HID) {
        atomicAdd(&g_stats[tid], s_sum[tid]);
        atomicAdd(&g_stats[HID + tid], s_sq[tid]);
    }
}

// ---------------- fused layer (layers 1,2): gather raw v, GEMM1, GEMM2 ------
// u = relu( aggv @ (sc⊙W1) + (1+deg_r)·(sf@W1)_c + b1_c )
// vout = relu( u @ W2 + b2 ) ; stats[layer]
// IN = g_BA or g_BB (templated by flag), OUT = the other.
template <bool IN_IS_A>
__global__ void __launch_bounds__(128) fused_layer_kernel(
    const float* __restrict__ gamma, const float* __restrict__ beta,
    const float* __restrict__ w1, const float* __restrict__ b1,
    const float* __restrict__ w2, const float* __restrict__ b2,
    int stats_layer, int layer)
{
    extern __shared__ float smem[];
    float* w_sh = smem;                 // [64][64] : W1f, later W2
    float* t_sh = smem + HID * HID;     // [128][64]: aggv, later u
    __shared__ float sc[HID], sf[HID], sfw1[HID];
    __shared__ float degs[128];
    __shared__ float s_sum[HID];
    __shared__ float s_sq[HID];
    int tid = threadIdx.x;

    const float* vin = IN_IS_A ? g_BA : g_BB;
    float* vout      = IN_IS_A ? g_BB : g_BA;

    // BN fold from stats of previous layer
    if (tid < HID) {
        const float* stats = g_stats + stats_layer * 2 * HID;
        float inv_n = 1.f / (float)N_NODES;
        float mu  = stats[tid] * inv_n;
        float var = stats[HID + tid] * inv_n - mu * mu;
        float s = gamma[tid] * rsqrtf(var + BN_EPS);
        sc[tid] = s;
        sf[tid] = beta[tid] - mu * s;
        s_sum[tid] = 0.f; s_sq[tid] = 0.f;
    }
    __syncthreads();

    // W1f = sc (row) ⊙ W1
    for (int i = tid; i < HID * HID / 4; i += 128) {
        float4 v = ((const float4*)w1)[i];
        float s = sc[i >> 4];            // row k of element 4i: (4i)/64
        v.x *= s; v.y *= s; v.z *= s; v.w *= s;
        ((float4*)w_sh)[i] = v;
    }
    // sfw1[c] = sum_k sf[k] * W1[k][c]
    if (tid < HID) {
        float b = 0.f;
#pragma unroll 8
        for (int k = 0; k < HID; k++)
            b += sf[k] * __ldg(&w1[k * HID + tid]);
        sfw1[tid] = b;
    }

    int rowbase = blockIdx.x * 128;
    int nrows = N_NODES - rowbase; if (nrows > 128) nrows = 128;

    // gather RAW aggv into t_sh (R6-exact loop, no bias/relu); record deg
    for (int it = 0; it < 8; it++) {
        int task = it * 128 + tid;
        int row = task >> 3;
        int c = (task & 7) * 8;
        float4 a0 = make_float4(0.f, 0.f, 0.f, 0.f), a1 = a0;
        if (row < nrows) {
            int node = rowbase + row;
            long base = (long)node * HID + c;
            a0 = *(const float4*)&vin[base];
            a1 = *(const float4*)&vin[base + 4];
            int p = g_off[node], end = g_off[node + 1];
            if (c == 0) degs[row] = (float)(1 + end - p);
            for (; p + 2 <= end; p += 2) {
                int s0 = __ldg(&g_csr[p]);
                int s1 = __ldg(&g_csr[p + 1]);
                const float4* t0 = (const float4*)(vin + (long)s0 * HID + c);
                const float4* t1 = (const float4*)(vin + (long)s1 * HID + c);
                float4 v00 = __ldg(t0), v01 = __ldg(t0 + 1);
                float4 v10 = __ldg(t1), v11 = __ldg(t1 + 1);
                add4(a0, v00); add4(a1, v01);
                add4(a0, v10); add4(a1, v11);
            }
            if (p < end) {
                int s0 = __ldg(&g_csr[p]);
                const float4* t0 = (const float4*)(vin + (long)s0 * HID + c);
                add4(a0, __ldg(t0)); add4(a1, __ldg(t0 + 1));
            }
        }
        *(float4*)&t_sh[row * HID + c]     = a0;
        *(float4*)&t_sh[row * HID + c + 4] = a1;
    }
    __syncthreads();

    int rg = tid >> 3, cg = tid & 7;
    int r0 = rg * 8, c0 = cg * 8;

    // GEMM1: acc = aggv @ W1f
    float acc[8][8];
#pragma unroll
    for (int r = 0; r < 8; r++)
#pragma unroll
        for (int j = 0; j < 8; j++) acc[r][j] = 0.f;

    for (int k = 0; k < HID; k += 4) {
        float4 av[8];
#pragma unroll
        for (int r = 0; r < 8; r++)
            av[r] = *(const float4*)&t_sh[(r0 + r) * HID + k];
#pragma unroll
        for (int kk = 0; kk < 4; kk++) {
            float4 w0 = *(const float4*)&w_sh[(k + kk) * HID + c0];
            float4 w1v = *(const float4*)&w_sh[(k + kk) * HID + c0 + 4];
#pragma unroll
            for (int r = 0; r < 8; r++) {
                float a = (kk == 0) ? av[r].x : (kk == 1) ? av[r].y
                         : (kk == 2) ? av[r].z : av[r].w;
                acc[r][0] += a * w0.x;  acc[r][1] += a * w0.y;
                acc[r][2] += a * w0.z;  acc[r][3] += a * w0.w;
                acc[r][4] += a * w1v.x; acc[r][5] += a * w1v.y;
                acc[r][6] += a * w1v.z; acc[r][7] += a * w1v.w;
            }
        }
    }
    // u = relu(acc + n_r * sfw1[c] + b1[c]); keep in regs until after sync
    float4 p0 = *(const float4*)&sfw1[c0];
    float4 p1 = *(const float4*)&sfw1[c0 + 4];
    float4 q0 = *(const float4*)&b1[c0];
    float4 q1 = *(const float4*)&b1[c0 + 4];
    float u[8][8];
#pragma unroll
    for (int r = 0; r < 8; r++) {
        float n = degs[r0 + r];
        u[r][0] = fmaxf(acc[r][0] + n * p0.x + q0.x, 0.f);
        u[r][1] = fmaxf(acc[r][1] + n * p0.y + q0.y, 0.f);
        u[r][2] = fmaxf(acc[r][2] + n * p0.z + q0.z, 0.f);
        u[r][3] = fmaxf(acc[r][3] + n * p0.w + q0.w, 0.f);
        u[r][4] = fmaxf(acc[r][4] + n * p1.x + q1.x, 0.f);
        u[r][5] = fmaxf(acc[r][5] + n * p1.y + q1.y, 0.f);
        u[r][6] = fmaxf(acc[r][6] + n * p1.z + q1.z, 0.f);
        u[r][7] = fmaxf(acc[r][7] + n * p1.w + q1.w, 0.f);
    }
    __syncthreads();   // all reads of t_sh/w_sh done

    // store u into t_sh; load W2 into w_sh
#pragma unroll
    for (int r = 0; r < 8; r++) {
        *(float4*)&t_sh[(r0 + r) * HID + c0]     = make_float4(u[r][0], u[r][1], u[r][2], u[r][3]);
        *(float4*)&t_sh[(r0 + r) * HID + c0 + 4] = make_float4(u[r][4], u[r][5], u[r][6], u[r][7]);
    }
    for (int i = tid; i < HID * HID / 4; i += 128)
        ((float4*)w_sh)[i] = ((const float4*)w2)[i];
    __syncthreads();

    // GEMM2
#pragma unroll
    for (int r = 0; r < 8; r++)
#pragma unroll
        for (int j = 0; j < 8; j++) acc[r][j] = 0.f;

    for (int k = 0; k < HID; k += 4) {
        float4 av[8];
#pragma unroll
        for (int r = 0; r < 8; r++)
            av[r] = *(const float4*)&t_sh[(r0 + r) * HID + k];
#pragma unroll
        for (int kk = 0; kk < 4; kk++) {
            float4 w0 = *(const float4*)&w_sh[(k + kk) * HID + c0];
            float4 w1v = *(const float4*)&w_sh[(k + kk) * HID + c0 + 4];
#pragma unroll
            for (int r = 0; r < 8; r++) {
                float a = (kk == 0) ? av[r].x : (kk == 1) ? av[r].y
                         : (kk == 2) ? av[r].z : av[r].w;
                acc[r][0] += a * w0.x;  acc[r][1] += a * w0.y;
                acc[r][2] += a * w0.z;  acc[r][3] += a * w0.w;
                acc[r][4] += a * w1v.x; acc[r][5] += a * w1v.y;
                acc[r][6] += a * w1v.z; acc[r][7] += a * w1v.w;
            }
        }
    }

    float4 bb0 = *(const float4*)&b2[c0];
    float4 bb1 = *(const float4*)&b2[c0 + 4];
    float ls[8] = {0,0,0,0,0,0,0,0};
    float lq[8] = {0,0,0,0,0,0,0,0};
#pragma unroll
    for (int r = 0; r < 8; r++) {
        if (r0 + r < nrows) {
            float o[8];
            o[0] = fmaxf(acc[r][0] + bb0.x, 0.f); o[1] = fmaxf(acc[r][1] + bb0.y, 0.f);
            o[2] = fmaxf(acc[r][2] + bb0.z, 0.f); o[3] = fmaxf(acc[r][3] + bb0.w, 0.f);
            o[4] = fmaxf(acc[r][4] + bb1.x, 0.f); o[5] = fmaxf(acc[r][5] + bb1.y, 0.f);
            o[6] = fmaxf(acc[r][6] + bb1.z, 0.f); o[7] = fmaxf(acc[r][7] + bb1.w, 0.f);
            long off = (long)(rowbase + r0 + r) * HID + c0;
            *(float4*)&vout[off]     = make_float4(o[0], o[1], o[2], o[3]);
            *(float4*)&vout[off + 4] = make_float4(o[4], o[5], o[6], o[7]);
#pragma unroll
            for (int j = 0; j < 8; j++) { ls[j] += o[j]; lq[j] += o[j] * o[j]; }
        }
    }
#pragma unroll
    for (int j = 0; j < 8; j++) {
        atomicAdd(&s_sum[c0 + j], ls[j]);
        atomicAdd(&s_sq[c0 + j],  lq[j]);
    }
    __syncthreads();
    float* stats = g_stats + layer * 2 * HID;
    if (tid < HID) {
        atomicAdd(&stats[tid], s_sum[tid]);
        atomicAdd(&stats[HID + tid], s_sq[tid]);
    }
}

// ---------------- pool: run-length segment max over g_BA (layer-2 out) ------
__global__ void __launch_bounds__(256) pool_kernel(
    const int* __restrict__ batch,
    const float* __restrict__ gamma, const float* __restrict__ beta)
{
    __shared__ float sc[HID], sf[HID];
    int tid = threadIdx.x;
    if (tid < HID) {
        const float* stats = g_stats + 2 * 2 * HID;   // layer 2
        float inv_n = 1.f / (float)N_NODES;
        float mu  = stats[tid] * inv_n;
        float var = stats[HID + tid] * inv_n - mu * mu;
        float s = gamma[tid] * rsqrtf(var + BN_EPS);
        sc[tid] = s;
        sf[tid] = beta[tid] - mu * s;
    }
    __syncthreads();

    int base = blockIdx.x * 128;
    int r = tid >> 6;
    int c = tid & 63;
    float cur = -INFINITY;
    int curg = -1;
    int lim = base + 128; if (lim > N_NODES) lim = N_NODES;
    for (int n = base + r; n < lim; n += 4) {
        int g = __ldg(&batch[n]);
        float v = g_BA[(long)n * HID + c] * sc[c] + sf[c];
        if (g != curg) {
            if (curg >= 0) atomicMaxF(&g_pooled[curg * HID + c], cur);
            curg = g; cur = v;
        } else {
            cur = fmaxf(cur, v);
        }
    }
    if (curg >= 0) atomicMaxF(&g_pooled[curg * HID + c], cur);
}

// ---------------- head ------------------------------------------------------
__global__ void __launch_bounds__(128) head_kernel(
    const float* __restrict__ lin1_w, const float* __restrict__ lin1_b,
    const float* __restrict__ lin2_w, const float* __restrict__ lin2_b,
    float* __restrict__ out)
{
    __shared__ float w1_sh[HID * HID];
    __shared__ float w2_sh[HID * OUT_F];
    __shared__ float p_sh[4][HID];
    __shared__ float h_sh[4][HID];
    int tid = threadIdx.x, warp = tid >> 5, lane = tid & 31;

    for (int i = tid; i < HID * HID / 4; i += 128)
        ((float4*)w1_sh)[i] = ((const float4*)lin1_w)[i];
    for (int i = tid; i < HID * OUT_F / 4; i += 128)
        ((float4*)w2_sh)[i] = ((const float4*)lin2_w)[i];

    int g = blockIdx.x * 4 + warp;
    float p0 = g_pooled[g * HID + lane];
    float p1 = g_pooled[g * HID + lane + 32];
    if (!isfinite(p0)) p0 = 0.f;
    if (!isfinite(p1)) p1 = 0.f;
    p_sh[warp][lane] = p0;
    p_sh[warp][lane + 32] = p1;
    __syncthreads();

    float acc0 = lin1_b[lane], acc1 = lin1_b[lane + 32];
#pragma unroll 8
    for (int k = 0; k < HID; k++) {
        float pv = p_sh[warp][k];
        acc0 += pv * w1_sh[k * HID + lane];
        acc1 += pv * w1_sh[k * HID + lane + 32];
    }
    h_sh[warp][lane]      = fmaxf(acc0, 0.f);
    h_sh[warp][lane + 32] = fmaxf(acc1, 0.f);
    __syncwarp();

    if (lane < OUT_F) {
        float acc = lin2_b[lane];
#pragma unroll 8
        for (int k = 0; k < HID; k++)
            acc += h_sh[warp][k] * w2_sh[k * OUT_F + lane];
        out[g * OUT_F + lane] = acc;
    }
}

// ---------------- launch ----------------------------------------------------
extern "C" void kernel_launch(void* const* d_in, const int* in_sizes, int n_in,
                              void* d_out, int out_size)
{
    const float* x     = (const float*)d_in[0];
    const int*   ei    = (const int*)d_in[1];    // int32 (JAX x64 disabled)
    const int*   batch = (const int*)d_in[2];
    const float* l0_w1 = (const float*)d_in[3];
    const float* l0_b1 = (const float*)d_in[4];
    const float* l0_w2 = (const float*)d_in[5];
    const float* l0_b2 = (const float*)d_in[6];
    const float* l0_g  = (const float*)d_in[7];
    const float* l0_be = (const float*)d_in[8];
    const float* ws1   = (const float*)d_in[9];
    const float* bs1   = (const float*)d_in[10];
    const float* ws2   = (const float*)d_in[11];
    const float* bs2   = (const float*)d_in[12];
    const float* gms   = (const float*)d_in[13];
    const float* bts   = (const float*)d_in[14];
    const float* lin1w = (const float*)d_in[15];
    const float* lin1b = (const float*)d_in[16];
    const float* lin2w = (const float*)d_in[17];
    const float* lin2b = (const float*)d_in[18];
    float* out = (float*)d_out;

    const int TILE_BLOCKS = (N_NODES + 127) / 128;          // 391
    const int EDGE_BLOCKS = (N_EDGES + 255) / 256;          // 3125
    const int SCANA_BLOCKS = (N_GRAPHS * HID + 255) / 256;  // 250

    const int SMEM_G1_L0 = (F_INPUT * HID + 128 * F_INPUT) * 4;  // 96 KB
    const int SMEM_48K   = (HID * HID + 128 * HID) * 4;          // 48 KB
    cudaFuncSetAttribute(gemm1_l0_kernel,
                         cudaFuncAttributeMaxDynamicSharedMemorySize, SMEM_G1_L0);
    cudaFuncSetAttribute(agg_gemm2_l0_kernel,
                         cudaFuncAttributeMaxDynamicSharedMemorySize, SMEM_48K);
    cudaFuncSetAttribute(fused_layer_kernel<true>,
                         cudaFuncAttributeMaxDynamicSharedMemorySize, SMEM_48K);
    cudaFuncSetAttribute(fused_layer_kernel<false>,
                         cudaFuncAttributeMaxDynamicSharedMemorySize, SMEM_48K);

    // ---- CSR build (+ pooled/stats init riding on scanA) ----
    hist_kernel<<<EDGE_BLOCKS, 256>>>(ei);
    scanA_kernel<<<SCANA_BLOCKS, 256>>>();
    scanC_kernel<<<NBLK256, 256>>>();
    fill_kernel<<<EDGE_BLOCKS, 256>>>(ei);

    // ---- layer 0: t0 = x@W1 -> BB; agg+MLP2 -> BA (stats 0) ----
    gemm1_l0_kernel<<<TILE_BLOCKS, 128, SMEM_G1_L0>>>(x, l0_w1);
    agg_gemm2_l0_kernel<<<TILE_BLOCKS, 128, SMEM_48K>>>(l0_b1, l0_w2, l0_b2);

    // ---- layer 1: BA -> BB (stats 1; BN from stats 0) ----
    fused_layer_kernel<true><<<TILE_BLOCKS, 128, SMEM_48K>>>(
        l0_g, l0_be, ws1, bs1, ws2, bs2, 0, 1);

    // ---- layer 2: BB -> BA (stats 2; BN from stats 1) ----
    fused_layer_kernel<false><<<TILE_BLOCKS, 128, SMEM_48K>>>(
        gms, bts, ws1 + HID * HID, bs1 + HID, ws2 + HID * HID, bs2 + HID, 1, 2);

    // ---- pool (BN layer 2 inline) + head ----
    pool_kernel<<<TILE_BLOCKS, 256>>>(batch, gms + HID, bts + HID);
    head_kernel<<<N_GRAPHS / 4, 128>>>(lin1w, lin1b, lin2w, lin2b, out);
}